// round 15
// baseline (speedup 1.0000x reference)
#include <cuda_runtime.h>
#include <cuda_fp16.h>
#include <cstdint>

#define NOBJ 25
#define ROWF 100          // floats per canvas row (25*4)
#define SPC  128          // samples per CTA (8 m-tiles)
#define KDIM 80           // padded K: [h(64) | x(4) | 1 | 0-pad(11)] = 5 x k16
#define ASTR 88           // fp16 row stride (176 B -> conflict-free ldmatrix)

// dynamic smem (halves): sB[256*88] | sA0[128*88] | sA1[128*88] | sSeq (float4, 16B aligned)
#define SB_H   (256 * ASTR)              // 22528 halves
#define SA_H   (SPC * ASTR)              // 11264 halves
#define OFF_A0 SB_H
#define OFF_A1 (SB_H + SA_H)
#define OFF_SEQ_BYTES ((SB_H + 2 * SA_H) * 2)            // 90112 B (16B aligned)
#define SMEM_TOTAL (OFF_SEQ_BYTES + SPC * NOBJ * 16)     // 141312 B

__device__ int    g_Tmax;
__device__ __half g_Bmat[256 * KDIM];   // folded weight matrix, gate-permuted rows, fp16

// ---------------- helpers ----------------
__device__ __forceinline__ void mma16(float& d0, float& d1, float& d2, float& d3,
                                      uint32_t a0, uint32_t a1, uint32_t a2, uint32_t a3,
                                      uint32_t b0, uint32_t b1) {
    asm volatile("mma.sync.aligned.m16n8k16.row.col.f32.f16.f16.f32 "
                 "{%0,%1,%2,%3}, {%4,%5,%6,%7}, {%8,%9}, {%0,%1,%2,%3};"
                 : "+f"(d0), "+f"(d1), "+f"(d2), "+f"(d3)
                 : "r"(a0), "r"(a1), "r"(a2), "r"(a3), "r"(b0), "r"(b1));
}

__device__ __forceinline__ void ldm_x4(uint32_t& r0, uint32_t& r1, uint32_t& r2, uint32_t& r3,
                                       uint32_t addr) {
    asm volatile("ldmatrix.sync.aligned.m8n8.x4.shared.b16 {%0,%1,%2,%3}, [%4];"
                 : "=r"(r0), "=r"(r1), "=r"(r2), "=r"(r3) : "r"(addr));
}

// packed fp16x2 tanh (MUFU, one op for two values)
__device__ __forceinline__ uint32_t h2tanh(uint32_t x) {
    uint32_t y;
    asm("tanh.approx.f16x2 %0, %1;" : "=r"(y) : "r"(x));
    return y;
}
__device__ __forceinline__ uint32_t pack_h2(float lo, float hi) {
    __half2 h = __floats2half2_rn(lo, hi);
    return *reinterpret_cast<uint32_t*>(&h);
}
__device__ __forceinline__ float2 unpack_h2(uint32_t v) {
    __half2 h = *reinterpret_cast<__half2*>(&v);
    return __half22float2(h);
}

// ---------------- Kernel 0: folded, gate-permuted B matrix [256][80] fp16 ----------------
// n-row mapping: tile=n>>3, pair=(n&7)>>1, which=n&1; u=((tile>>1)<<2)+pair;
// gate = even tile ? (which?f:i) : (which?o:g)   [torch i,f,g,o]
// Row: [0..63]=W_hh[wr][k], [64..67]=(W_ih@W_emb)[wr][d], [68]=total bias, [69..79]=0
__global__ void precompute_kernel(const float* __restrict__ W_emb, const float* __restrict__ b_emb,
                                  const float* __restrict__ W_ih,  const float* __restrict__ W_hh,
                                  const float* __restrict__ b_ih,  const float* __restrict__ b_hh) {
    const int n = threadIdx.x;            // 256 threads, one B-row each
    if (n == 0) g_Tmax = 0;
    const int tile = n >> 3, pair = (n & 7) >> 1, which = n & 1;
    const int u = ((tile >> 1) << 2) + pair;
    const int gate = (tile & 1) ? (2 + which) : which;
    const int wr = gate * 64 + u;

    __half* dst = g_Bmat + n * KDIM;
    for (int k = 0; k < 64; k++)
        dst[k] = __float2half_rn(W_hh[wr * 64 + k]);

    float a0 = 0.f, a1 = 0.f, a2 = 0.f, a3 = 0.f, bias = 0.f;
    for (int k = 0; k < 64; k++) {
        const float wih = W_ih[wr * 64 + k];
        a0 = fmaf(wih, W_emb[k * 4 + 0], a0);
        a1 = fmaf(wih, W_emb[k * 4 + 1], a1);
        a2 = fmaf(wih, W_emb[k * 4 + 2], a2);
        a3 = fmaf(wih, W_emb[k * 4 + 3], a3);
        bias = fmaf(wih, b_emb[k], bias);
    }
    bias += b_ih[wr] + b_hh[wr];
    dst[64] = __float2half_rn(a0);
    dst[65] = __float2half_rn(a1);
    dst[66] = __float2half_rn(a2);
    dst[67] = __float2half_rn(a3);
    dst[68] = __float2half_rn(bias);
    for (int k = 69; k < KDIM; k++) dst[k] = __float2half_rn(0.0f);
}

// ---------------- Kernel 1: batch-wide max valid-object count ----------------
__global__ void count_kernel(const float* __restrict__ canvas, int B) {
    __shared__ int smax;
    if (threadIdx.x == 0) smax = 0;
    __syncthreads();
    const int warp = blockIdx.x * (blockDim.x >> 5) + (threadIdx.x >> 5);
    const int lane = threadIdx.x & 31;
    if (warp < B) {
        int valid = 0;
        if (lane < NOBJ) {
            const float4 v = *reinterpret_cast<const float4*>(canvas + (size_t)warp * ROWF + lane * 4);
            valid = (((v.x + v.y) + v.z) + v.w >= 0.0f) ? 1 : 0;
        }
        const unsigned msk = __ballot_sync(0xFFFFFFFFu, valid);
        if (lane == 0 && msk) atomicMax(&smax, __popc(msk));
    }
    __syncthreads();
    if (threadIdx.x == 0 && smax > 0) atomicMax(&g_Tmax, smax);
}

// ---------------- Kernel 2: fp16 mma.sync LSTM, 128 samples/CTA, 512 threads ----------------
// Warp w: col-group wg=w&7 (gate cols [32wg,32wg+32) = units [8wg,8wg+8)),
//         m-half mh=w>>3 (samples mh*64 .. mh*64+63, 4 m-tiles).
// Thread (gid=lane>>2, tig=lane&3): units u0=8wg+tig, u1=u0+4.
// B fragments persistent in registers; mt-outer loop (R13 structure, single acc bank);
// epilogue activations via tanh.approx.f16x2 (half the MUFU ops), c-state exact fp32.
__global__ void __launch_bounds__(512, 1) lstm_kernel(const float* __restrict__ canvas,
                                                      float* __restrict__ out, int B) {
    extern __shared__ __half smh[];
    __half* sB = smh;
    __half* sAbuf[2] = { smh + OFF_A0, smh + OFF_A1 };
    float4* sSeq = reinterpret_cast<float4*>(reinterpret_cast<char*>(smh) + OFF_SEQ_BYTES);

    const int tid  = threadIdx.x;
    const int w    = tid >> 5, lane = tid & 31;
    const int wg   = w & 7, mh = w >> 3;
    const int gid  = lane >> 2, tig = lane & 3;
    const int u0   = wg * 8 + tig, u1 = u0 + 4;
    const int nw   = wg * 32;
    const int ctaBase = blockIdx.x * SPC;

    // ldmatrix lane addressing (b16 elements)
    const int r8 = lane & 7;
    const int a_row = ((lane >> 3) & 1) * 8 + r8;          // row within m-tile
    const int a_col = (lane >> 4) * 8;                     // fp16 col within k16 chunk
    const int b_rowp = ((lane >> 4)) * 8 + r8;             // row within 16-row n-pair
    const int b_col = ((lane >> 3) & 1) * 8;               // fp16 col within k16 chunk
    const uint32_t sBaddr = (uint32_t)__cvta_generic_to_shared(sB);
    const uint32_t sAaddr[2] = { (uint32_t)__cvta_generic_to_shared(sAbuf[0]),
                                 (uint32_t)__cvta_generic_to_shared(sAbuf[1]) };

    // Load B [256][80] -> sB [256][88]
    for (int i = tid; i < 256 * KDIM; i += 512) {
        const int n = i / KDIM, k = i - n * KDIM;
        sB[n * ASTR + k] = g_Bmat[i];
    }
    // Zero A buffers (cols 69..87 stay 0 forever; kc=4 reads 69..79 as zero-pad)
    for (int i = tid; i < 2 * SA_H; i += 512) smh[OFF_A0 + i] = __float2half_rn(0.0f);
    __syncthreads();
    const __half hone = __float2half_rn(1.0f);
    if (tid < SPC) { sAbuf[0][tid * ASTR + 68] = hone; sAbuf[1][tid * ASTR + 68] = hone; }

    // Compaction: 16 warps x 8 samples, stable-compact, pad -1
    #pragma unroll
    for (int m = 0; m < 8; m++) {
        const int s = w * 8 + m;
        const int b = ctaBase + s;
        float4 v = make_float4(-1.f, -1.f, -1.f, -1.f);
        int valid = 0;
        if (b < B && lane < NOBJ) {
            v = *reinterpret_cast<const float4*>(canvas + (size_t)b * ROWF + lane * 4);
            valid = (((v.x + v.y) + v.z) + v.w >= 0.0f) ? 1 : 0;
        }
        const unsigned msk = __ballot_sync(0xFFFFFFFFu, valid);
        const int cnt = __popc(msk);
        if (lane < NOBJ) {
            if (valid) sSeq[s * NOBJ + __popc(msk & ((1u << lane) - 1u))] = v;
            if (lane >= cnt) sSeq[s * NOBJ + lane] = make_float4(-1.f, -1.f, -1.f, -1.f);
        }
    }
    __syncthreads();   // sB fully written before fragment preload

    // B fragments: persistent registers for the whole kernel (5 kc x 2 pairs x 4 = 40 regs)
    uint32_t bfr[5][2][4];
    #pragma unroll
    for (int kc = 0; kc < 5; kc++)
        #pragma unroll
        for (int p = 0; p < 2; p++) {
            const uint32_t addr = sBaddr +
                (((nw + p * 16 + b_rowp) * ASTR) + kc * 16 + b_col) * 2u;
            ldm_x4(bfr[kc][p][0], bfr[kc][p][1], bfr[kc][p][2], bfr[kc][p][3], addr);
        }

    float c_[16];
    #pragma unroll
    for (int i = 0; i < 16; i++) c_[i] = 0.f;

    const int T = g_Tmax;

    // x_0 into buffer 0 (fp16, 8B store)
    if (tid < SPC) {
        const float4 x = sSeq[tid * NOBJ + 0];
        __half2 h01 = __floats2half2_rn(x.x, x.y);
        __half2 h23 = __floats2half2_rn(x.z, x.w);
        uint2 pk = make_uint2(*reinterpret_cast<uint32_t*>(&h01),
                              *reinterpret_cast<uint32_t*>(&h23));
        *reinterpret_cast<uint2*>(sAbuf[0] + tid * ASTR + 64) = pk;
    }
    __syncthreads();

    for (int t = 0; t < T; t++) {
        const uint32_t aBase = sAaddr[t & 1];
        __half* sAn = sAbuf[(t & 1) ^ 1];
        const bool last = (t == T - 1);

        // mt-outer: one m-tile accumulated (16 live acc regs), then its epilogue
        #pragma unroll
        for (int mt = 0; mt < 4; mt++) {
            float acc[4][4];
            #pragma unroll
            for (int nt = 0; nt < 4; nt++)
                #pragma unroll
                for (int e = 0; e < 4; e++) acc[nt][e] = 0.f;

            #pragma unroll
            for (int kc = 0; kc < 5; kc++) {
                uint32_t a0, a1, a2, a3;
                const uint32_t addr = aBase +
                    (((mh * 64 + mt * 16 + a_row) * ASTR) + kc * 16 + a_col) * 2u;
                ldm_x4(a0, a1, a2, a3, addr);
                #pragma unroll
                for (int nt = 0; nt < 4; nt++)
                    mma16(acc[nt][0], acc[nt][1], acc[nt][2], acc[nt][3],
                          a0, a1, a2, a3,
                          bfr[kc][nt >> 1][(nt & 1) * 2], bfr[kc][nt >> 1][(nt & 1) * 2 + 1]);
            }

            // --- f16x2 epilogue: 10 packed MUFU per m-tile (was 20 scalar) ---
            const int s0 = mh * 64 + mt * 16 + gid;
            uint32_t t_if[4], t_og[4];
            #pragma unroll
            for (int q = 0; q < 4; q++) {
                const int ntA = (q >> 1) * 2;
                const int e   = (q & 1) * 2;
                const float iv = acc[ntA][e + 0];
                const float fv = acc[ntA][e + 1];
                const float gv = acc[ntA + 1][e + 0];
                const float ov = acc[ntA + 1][e + 1];
                t_if[q] = h2tanh(pack_h2(0.5f * iv, 0.5f * fv));
                t_og[q] = h2tanh(pack_h2(0.5f * ov, gv));
            }
            float cn[4];
            #pragma unroll
            for (int q = 0; q < 4; q++) {
                const float2 sif = unpack_h2(t_if[q]);
                const float2 sog = unpack_h2(t_og[q]);
                const float sig_i = fmaf(sif.x, 0.5f, 0.5f);
                const float sig_f = fmaf(sif.y, 0.5f, 0.5f);
                cn[q] = sig_f * c_[mt * 4 + q] + sig_i * sog.y;   // c-state exact fp32
                c_[mt * 4 + q] = cn[q];
            }
            const uint32_t tc01 = h2tanh(pack_h2(cn[0], cn[1]));
            const uint32_t tc23 = h2tanh(pack_h2(cn[2], cn[3]));
            float tcv[4];
            { const float2 f01 = unpack_h2(tc01), f23 = unpack_h2(tc23);
              tcv[0] = f01.x; tcv[1] = f01.y; tcv[2] = f23.x; tcv[3] = f23.y; }
            #pragma unroll
            for (int q = 0; q < 4; q++) {
                const float2 sog = unpack_h2(t_og[q]);
                const float sig_o = fmaf(sog.x, 0.5f, 0.5f);
                const float hn = sig_o * tcv[q];
                const int s = s0 + (q & 1) * 8;
                const int u = (q >> 1) ? u1 : u0;
                sAn[s * ASTR + u] = __float2half_rn(hn);
                if (last) {
                    const int b = ctaBase + s;
                    if (b < B) out[(size_t)b * 64 + u] = hn;
                }
            }
        }

        // x_{t+1} into next buffer (fp16)
        if (t + 1 < T && tid < SPC) {
            const float4 x = sSeq[tid * NOBJ + t + 1];
            __half2 h01 = __floats2half2_rn(x.x, x.y);
            __half2 h23 = __floats2half2_rn(x.z, x.w);
            uint2 pk = make_uint2(*reinterpret_cast<uint32_t*>(&h01),
                                  *reinterpret_cast<uint32_t*>(&h23));
            *reinterpret_cast<uint2*>(sAn + tid * ASTR + 64) = pk;
        }

        __syncthreads();   // single barrier per step
    }

    // T == 0: no steps ran, h = 0 everywhere (out is poisoned -> must write)
    if (T == 0) {
        for (int i = tid; i < SPC * 16; i += 512) {
            const int s = i >> 4, q = i & 15;
            const int b = ctaBase + s;
            if (b < B)
                *reinterpret_cast<float4*>(out + (size_t)b * 64 + q * 4) =
                    make_float4(0.f, 0.f, 0.f, 0.f);
        }
    }
}

// ---------------- launch ----------------
extern "C" void kernel_launch(void* const* d_in, const int* in_sizes, int n_in,
                              void* d_out, int out_size) {
    const float* canvas = (const float*)d_in[0];
    const float* W_emb  = (const float*)d_in[1];
    const float* b_emb  = (const float*)d_in[2];
    const float* W_ih   = (const float*)d_in[3];
    const float* W_hh   = (const float*)d_in[4];
    const float* b_ih   = (const float*)d_in[5];
    const float* b_hh   = (const float*)d_in[6];
    float* out = (float*)d_out;

    const int B = in_sizes[0] / ROWF;

    cudaFuncSetAttribute(lstm_kernel, cudaFuncAttributeMaxDynamicSharedMemorySize, SMEM_TOTAL);

    precompute_kernel<<<1, 256>>>(W_emb, b_emb, W_ih, W_hh, b_ih, b_hh);
    count_kernel<<<(B + 7) / 8, 256>>>(canvas, B);
    lstm_kernel<<<(B + SPC - 1) / SPC, 512, SMEM_TOTAL>>>(canvas, out, B);
}

// round 16
// speedup vs baseline: 1.2726x; 1.2726x over previous
#include <cuda_runtime.h>
#include <cuda_fp16.h>
#include <cstdint>

#define NOBJ 25
#define ROWF 100          // floats per canvas row (25*4)
#define SPC  64           // samples per CTA (4 m-tiles)
#define KDIM 80           // padded K: [h(64) | x(4) | 1 | 0-pad(11)] = 5 x k16
#define ASTR 88           // fp16 row stride (176 B -> conflict-free ldmatrix)

// smem bytes: UNION( sB[256*88*2]=45056 | sSeq[64*25*16]=25600 ) | sA0 | sA1
#define UNION_BYTES 45056
#define SA_BYTES (SPC * ASTR * 2)            // 11264
#define OFF_A0_B UNION_BYTES                 // 45056
#define OFF_A1_B (UNION_BYTES + SA_BYTES)    // 56320
#define SMEM_TOTAL (UNION_BYTES + 2 * SA_BYTES)   // 67584 B -> 2 CTAs/SM

__device__ int    g_Tmax;
__device__ __half g_Bmat[256 * KDIM];   // folded weight matrix, gate-permuted rows, fp16

// ---------------- helpers ----------------
__device__ __forceinline__ void mma16(float& d0, float& d1, float& d2, float& d3,
                                      uint32_t a0, uint32_t a1, uint32_t a2, uint32_t a3,
                                      uint32_t b0, uint32_t b1) {
    asm volatile("mma.sync.aligned.m16n8k16.row.col.f32.f16.f16.f32 "
                 "{%0,%1,%2,%3}, {%4,%5,%6,%7}, {%8,%9}, {%0,%1,%2,%3};"
                 : "+f"(d0), "+f"(d1), "+f"(d2), "+f"(d3)
                 : "r"(a0), "r"(a1), "r"(a2), "r"(a3), "r"(b0), "r"(b1));
}

__device__ __forceinline__ void ldm_x4(uint32_t& r0, uint32_t& r1, uint32_t& r2, uint32_t& r3,
                                       uint32_t addr) {
    asm volatile("ldmatrix.sync.aligned.m8n8.x4.shared.b16 {%0,%1,%2,%3}, [%4];"
                 : "=r"(r0), "=r"(r1), "=r"(r2), "=r"(r3) : "r"(addr));
}

__device__ __forceinline__ float tanhapx(float x) {
    float y; asm("tanh.approx.f32 %0, %1;" : "=f"(y) : "f"(x)); return y;
}
__device__ __forceinline__ float sigm_t(float x) {
    return fmaf(tanhapx(0.5f * x), 0.5f, 0.5f);
}

// ---------------- Kernel 0: folded, gate-permuted B matrix [256][80] fp16 ----------------
// n-row mapping: tile=n>>3, pair=(n&7)>>1, which=n&1; u=((tile>>1)<<2)+pair;
// gate = even tile ? (which?f:i) : (which?o:g)   [torch i,f,g,o]
// Row: [0..63]=W_hh[wr][k], [64..67]=(W_ih@W_emb)[wr][d], [68]=total bias, [69..79]=0
__global__ void precompute_kernel(const float* __restrict__ W_emb, const float* __restrict__ b_emb,
                                  const float* __restrict__ W_ih,  const float* __restrict__ W_hh,
                                  const float* __restrict__ b_ih,  const float* __restrict__ b_hh) {
    const int n = threadIdx.x;            // 256 threads, one B-row each
    if (n == 0) g_Tmax = 0;
    const int tile = n >> 3, pair = (n & 7) >> 1, which = n & 1;
    const int u = ((tile >> 1) << 2) + pair;
    const int gate = (tile & 1) ? (2 + which) : which;
    const int wr = gate * 64 + u;

    __half* dst = g_Bmat + n * KDIM;
    for (int k = 0; k < 64; k++)
        dst[k] = __float2half_rn(W_hh[wr * 64 + k]);

    float a0 = 0.f, a1 = 0.f, a2 = 0.f, a3 = 0.f, bias = 0.f;
    for (int k = 0; k < 64; k++) {
        const float wih = W_ih[wr * 64 + k];
        a0 = fmaf(wih, W_emb[k * 4 + 0], a0);
        a1 = fmaf(wih, W_emb[k * 4 + 1], a1);
        a2 = fmaf(wih, W_emb[k * 4 + 2], a2);
        a3 = fmaf(wih, W_emb[k * 4 + 3], a3);
        bias = fmaf(wih, b_emb[k], bias);
    }
    bias += b_ih[wr] + b_hh[wr];
    dst[64] = __float2half_rn(a0);
    dst[65] = __float2half_rn(a1);
    dst[66] = __float2half_rn(a2);
    dst[67] = __float2half_rn(a3);
    dst[68] = __float2half_rn(bias);
    for (int k = 69; k < KDIM; k++) dst[k] = __float2half_rn(0.0f);
}

// ---------------- Kernel 1: batch-wide max valid-object count ----------------
__global__ void count_kernel(const float* __restrict__ canvas, int B) {
    __shared__ int smax;
    if (threadIdx.x == 0) smax = 0;
    __syncthreads();
    const int warp = blockIdx.x * (blockDim.x >> 5) + (threadIdx.x >> 5);
    const int lane = threadIdx.x & 31;
    if (warp < B) {
        int valid = 0;
        if (lane < NOBJ) {
            const float4 v = *reinterpret_cast<const float4*>(canvas + (size_t)warp * ROWF + lane * 4);
            valid = (((v.x + v.y) + v.z) + v.w >= 0.0f) ? 1 : 0;
        }
        const unsigned msk = __ballot_sync(0xFFFFFFFFu, valid);
        if (lane == 0 && msk) atomicMax(&smax, __popc(msk));
    }
    __syncthreads();
    if (threadIdx.x == 0 && smax > 0) atomicMax(&g_Tmax, smax);
}

// ---------------- Kernel 2: fp16 mma.sync LSTM, 64 samples/CTA, 256 threads, 2 CTAs/SM ----------------
// Warp w (0..7) owns gate cols [32w,32w+32) = units [8w,8w+8), all 4 m-tiles.
// Thread (gid=lane>>2, tig=lane&3): units u0=8w+tig, u1=u0+4.
// sB region is reused for sSeq after B fragments are preloaded to registers.
// Odd placement waves stagger by ~2500 cyc to anti-phase co-resident CTAs.
__global__ void __launch_bounds__(256, 2) lstm_kernel(const float* __restrict__ canvas,
                                                      float* __restrict__ out, int B) {
    extern __shared__ char smc[];
    __half* sB   = reinterpret_cast<__half*>(smc);                  // dead after bfr preload
    float4* sSeq = reinterpret_cast<float4*>(smc);                  // overlays sB
    __half* sAbuf[2] = { reinterpret_cast<__half*>(smc + OFF_A0_B),
                         reinterpret_cast<__half*>(smc + OFF_A1_B) };

    const int tid  = threadIdx.x;
    const int w    = tid >> 5, lane = tid & 31;
    const int gid  = lane >> 2, tig = lane & 3;
    const int u0   = w * 8 + tig, u1 = u0 + 4;
    const int nw   = w * 32;
    const int ctaBase = blockIdx.x * SPC;

    // ldmatrix lane addressing (b16 elements)
    const int r8 = lane & 7;
    const int a_row = ((lane >> 3) & 1) * 8 + r8;          // row within m-tile
    const int a_col = (lane >> 4) * 8;                     // fp16 col within k16 chunk
    const int b_rowp = ((lane >> 4)) * 8 + r8;             // row within 16-row n-pair
    const int b_col = ((lane >> 3) & 1) * 8;               // fp16 col within k16 chunk
    const uint32_t sBaddr = (uint32_t)__cvta_generic_to_shared(sB);
    const uint32_t sAaddr[2] = { (uint32_t)__cvta_generic_to_shared(sAbuf[0]),
                                 (uint32_t)__cvta_generic_to_shared(sAbuf[1]) };

    // Load B [256][80] -> sB [256][88]
    for (int i = tid; i < 256 * KDIM; i += 256) {
        const int n = i / KDIM, k = i - n * KDIM;
        sB[n * ASTR + k] = g_Bmat[i];
    }
    __syncthreads();   // sB complete before fragment preload

    // B fragments: persistent registers (5 kc x 2 pairs x 4 = 40 regs)
    uint32_t bfr[5][2][4];
    #pragma unroll
    for (int kc = 0; kc < 5; kc++)
        #pragma unroll
        for (int p = 0; p < 2; p++) {
            const uint32_t addr = sBaddr +
                (((nw + p * 16 + b_rowp) * ASTR) + kc * 16 + b_col) * 2u;
            ldm_x4(bfr[kc][p][0], bfr[kc][p][1], bfr[kc][p][2], bfr[kc][p][3], addr);
        }
    __syncthreads();   // ALL warps done reading sB before sSeq overwrites it

    // Zero A buffers (cols 69..87 stay 0 forever; kc=4 reads 69..79 as zero-pad)
    for (int i = tid; i < 2 * SPC * ASTR; i += 256)
        reinterpret_cast<__half*>(smc + OFF_A0_B)[i] = __float2half_rn(0.0f);

    // Compaction into sSeq (overlaying sB): 8 warps x 8 samples, stable-compact, pad -1
    #pragma unroll
    for (int m = 0; m < 8; m++) {
        const int s = w * 8 + m;
        const int b = ctaBase + s;
        float4 v = make_float4(-1.f, -1.f, -1.f, -1.f);
        int valid = 0;
        if (b < B && lane < NOBJ) {
            v = *reinterpret_cast<const float4*>(canvas + (size_t)b * ROWF + lane * 4);
            valid = (((v.x + v.y) + v.z) + v.w >= 0.0f) ? 1 : 0;
        }
        const unsigned msk = __ballot_sync(0xFFFFFFFFu, valid);
        const int cnt = __popc(msk);
        if (lane < NOBJ) {
            if (valid) sSeq[s * NOBJ + __popc(msk & ((1u << lane) - 1u))] = v;
            if (lane >= cnt) sSeq[s * NOBJ + lane] = make_float4(-1.f, -1.f, -1.f, -1.f);
        }
    }
    __syncthreads();

    // Bias column (68) = 1 in both A buffers; x_0 into buffer 0 (fp16)
    const __half hone = __float2half_rn(1.0f);
    if (tid < SPC) {
        sAbuf[0][tid * ASTR + 68] = hone;
        sAbuf[1][tid * ASTR + 68] = hone;
        const float4 x = sSeq[tid * NOBJ + 0];
        __half2 h01 = __floats2half2_rn(x.x, x.y);
        __half2 h23 = __floats2half2_rn(x.z, x.w);
        uint2 pk = make_uint2(*reinterpret_cast<uint32_t*>(&h01),
                              *reinterpret_cast<uint32_t*>(&h23));
        *reinterpret_cast<uint2*>(sAbuf[0] + tid * ASTR + 64) = pk;
    }

    float c_[16];
    #pragma unroll
    for (int i = 0; i < 16; i++) c_[i] = 0.f;

    const int T = g_Tmax;
    __syncthreads();

    // Phase stagger: odd placement waves delay ~2500 cyc so the two co-resident
    // CTAs on each SM run HMMA/MUFU phases anti-aligned instead of in lockstep.
    if ((blockIdx.x / 148) & 1) {
        const long long start = clock64();
        while (clock64() - start < 2500) {}
    }

    for (int t = 0; t < T; t++) {
        const uint32_t aBase = sAaddr[t & 1];
        __half* sAn = sAbuf[(t & 1) ^ 1];
        const bool last = (t == T - 1);

        // mt-outer: one m-tile accumulated (16 live acc regs), then its epilogue
        #pragma unroll
        for (int mt = 0; mt < 4; mt++) {
            float acc[4][4];
            #pragma unroll
            for (int nt = 0; nt < 4; nt++)
                #pragma unroll
                for (int e = 0; e < 4; e++) acc[nt][e] = 0.f;

            #pragma unroll
            for (int kc = 0; kc < 5; kc++) {
                uint32_t a0, a1, a2, a3;
                const uint32_t addr = aBase +
                    (((mt * 16 + a_row) * ASTR) + kc * 16 + a_col) * 2u;
                ldm_x4(a0, a1, a2, a3, addr);
                #pragma unroll
                for (int nt = 0; nt < 4; nt++)
                    mma16(acc[nt][0], acc[nt][1], acc[nt][2], acc[nt][3],
                          a0, a1, a2, a3,
                          bfr[kc][nt >> 1][(nt & 1) * 2], bfr[kc][nt >> 1][(nt & 1) * 2 + 1]);
            }

            const int s0 = mt * 16 + gid;
            #pragma unroll
            for (int q = 0; q < 4; q++) {
                const int ntA = (q >> 1) * 2;
                const int e   = (q & 1) * 2;
                const float iv = acc[ntA][e + 0];
                const float fv = acc[ntA][e + 1];
                const float gv = acc[ntA + 1][e + 0];
                const float ov = acc[ntA + 1][e + 1];
                const int ci = mt * 4 + q;
                const float cn = sigm_t(fv) * c_[ci] + sigm_t(iv) * tanhapx(gv);
                c_[ci] = cn;
                const float hn = sigm_t(ov) * tanhapx(cn);
                const int s = s0 + (q & 1) * 8;
                const int u = (q >> 1) ? u1 : u0;
                sAn[s * ASTR + u] = __float2half_rn(hn);
                if (last) {
                    const int b = ctaBase + s;
                    if (b < B) out[(size_t)b * 64 + u] = hn;
                }
            }
        }

        // x_{t+1} into next buffer (fp16)
        if (t + 1 < T && tid < SPC) {
            const float4 x = sSeq[tid * NOBJ + t + 1];
            __half2 h01 = __floats2half2_rn(x.x, x.y);
            __half2 h23 = __floats2half2_rn(x.z, x.w);
            uint2 pk = make_uint2(*reinterpret_cast<uint32_t*>(&h01),
                                  *reinterpret_cast<uint32_t*>(&h23));
            *reinterpret_cast<uint2*>(sAn + tid * ASTR + 64) = pk;
        }

        __syncthreads();   // single barrier per step (per-CTA only)
    }

    // T == 0: no steps ran, h = 0 everywhere (out is poisoned -> must write)
    if (T == 0) {
        for (int i = tid; i < SPC * 16; i += 256) {
            const int s = i >> 4, q = i & 15;
            const int b = ctaBase + s;
            if (b < B)
                *reinterpret_cast<float4*>(out + (size_t)b * 64 + q * 4) =
                    make_float4(0.f, 0.f, 0.f, 0.f);
        }
    }
}

// ---------------- launch ----------------
extern "C" void kernel_launch(void* const* d_in, const int* in_sizes, int n_in,
                              void* d_out, int out_size) {
    const float* canvas = (const float*)d_in[0];
    const float* W_emb  = (const float*)d_in[1];
    const float* b_emb  = (const float*)d_in[2];
    const float* W_ih   = (const float*)d_in[3];
    const float* W_hh   = (const float*)d_in[4];
    const float* b_ih   = (const float*)d_in[5];
    const float* b_hh   = (const float*)d_in[6];
    float* out = (float*)d_out;

    const int B = in_sizes[0] / ROWF;

    cudaFuncSetAttribute(lstm_kernel, cudaFuncAttributeMaxDynamicSharedMemorySize, SMEM_TOTAL);

    precompute_kernel<<<1, 256>>>(W_emb, b_emb, W_ih, W_hh, b_ih, b_hh);
    count_kernel<<<(B + 7) / 8, 256>>>(canvas, B);
    lstm_kernel<<<(B + SPC - 1) / SPC, 256, SMEM_TOTAL>>>(canvas, out, B);
}